// round 15
// baseline (speedup 1.0000x reference)
#include <cuda_runtime.h>
#include <cstdint>

// ---------------------------------------------------------------------------
// Contrast loss, fused:
//   a_i = zp1_i/|zp1_i| * (log2e/tau),  b_j = zp2_j/|zp2_j|
//   m[i][j] = 2^(a_i . b_j)
//   loss = LN2*( LAM*sum(lg2 rs) + (1-LAM)*sum(lg2 cs) - sum(a_i.b_i) ) / N
//
// Packed-row trick: g_ap row-pair interleaved {a_{2p,k}, a_{2p+1,k}}, g_bd
// duplicated {b_k, b_k}; one 8-deep fma.f32x2 chain = TWO dots.
//
// Pair kernel (this round): NO smem staging, NO barriers in the hot loop.
// Columns are read directly with __ldg LDG.128 (4 per 64B column; broadcast
// within each half-warp, L1-resident working set ~40KB per (SM, chunk)).
// Warps free-run so fma/MUFU/MIO phases of different warps interleave.
// Column reduction: 5-shfl value-splitting butterfly + one atomic per col.
// Zero-padded rows/cols contribute 2^0 = 1, cancelled in the sum inits.
// ---------------------------------------------------------------------------

#define TAU   0.5f
#define LAM   0.5f
#define EPS   1e-8f
#define LOG2E 1.4426950408889634f
#define LN2   0.6931471805599453f

#define MAXPAD 16384
#define NCHUNKS 16

__device__ __align__(16) float g_ap[MAXPAD * 8];    // row-pair interleaved
__device__ __align__(16) float g_bd[MAXPAD * 16];   // duplicated
__device__ float g_rs[MAXPAD];
__device__ float g_cs[MAXPAD];
__device__ float g_part[3];
__device__ unsigned int g_cnt;

typedef unsigned long long u64;
typedef unsigned int       u32;

__device__ __forceinline__ u64 mul2(u64 a, u64 b) {
    u64 r; asm("mul.rn.f32x2 %0, %1, %2;" : "=l"(r) : "l"(a), "l"(b)); return r;
}
__device__ __forceinline__ u64 fma2(u64 a, u64 b, u64 c) {
    u64 r; asm("fma.rn.f32x2 %0, %1, %2, %3;" : "=l"(r) : "l"(a), "l"(b), "l"(c));
    return r;
}
__device__ __forceinline__ u64 add2(u64 a, u64 b) {
    u64 r; asm("add.rn.f32x2 %0, %1, %2;" : "=l"(r) : "l"(a), "l"(b)); return r;
}

__device__ __forceinline__ float ex2(float x) {
    float r;
    asm("ex2.approx.ftz.f32 %0, %1;" : "=f"(r) : "f"(x));
    return r;
}
__device__ __forceinline__ float lg2(float x) {
    float r;
    asm("lg2.approx.f32 %0, %1;" : "=f"(r) : "f"(x));
    return r;
}

// ------------------------------- K1: projection ----------------------------
__global__ void proj_kernel(const float* __restrict__ z_mp,
                            const float* __restrict__ z_sc,
                            const float* __restrict__ W1,
                            const float* __restrict__ b1,
                            const float* __restrict__ W2,
                            const float* __restrict__ b2,
                            int N, int NpadC, float rs_init, float cs_init) {
    __shared__ float w1s[64], w2s[64], b1s[8], b2s[8];
    int t = threadIdx.x;
    if (t < 64) { w1s[t] = W1[t]; w2s[t] = W2[t]; }
    if (t < 8)  { b1s[t] = b1[t]; b2s[t] = b2[t]; }
    if (blockIdx.x == 0 && t < 3) g_part[t] = 0.0f;
    if (blockIdx.x == 0 && t == 3) g_cnt = 0u;
    __syncthreads();

    int idx = blockIdx.x * blockDim.x + t;
    if (idx >= 2 * NpadC) return;
    int side = (idx >= NpadC) ? 1 : 0;     // 0 = z_mp -> g_ap, 1 = z_sc -> g_bd
    int row  = side ? (idx - NpadC) : idx;

    if (!side) { g_rs[row] = rs_init; g_cs[row] = cs_init; }

    float o[8];
    if (row >= N) {
#pragma unroll
        for (int k = 0; k < 8; k++) o[k] = 0.0f;
    } else {
        const float* z = (side ? z_sc : z_mp) + row * 8;
        float zr[8];
#pragma unroll
        for (int d = 0; d < 8; d++) zr[d] = z[d];

        float h[8];
#pragma unroll
        for (int k = 0; k < 8; k++) {
            float s = b1s[k];
#pragma unroll
            for (int d = 0; d < 8; d++) s = fmaf(zr[d], w1s[k * 8 + d], s);
            h[k] = (s > 0.0f) ? s : (ex2(s * LOG2E) - 1.0f);   // ELU(alpha=1)
        }
        float nn = 0.0f;
#pragma unroll
        for (int j = 0; j < 8; j++) {
            float s = b2s[j];
#pragma unroll
            for (int k = 0; k < 8; k++) s = fmaf(h[k], w2s[j * 8 + k], s);
            o[j] = s;
            nn = fmaf(s, s, nn);
        }
        float scl = (side ? 1.0f : (LOG2E / TAU)) * rsqrtf(nn);
#pragma unroll
        for (int k = 0; k < 8; k++) o[k] *= scl;
    }

    if (!side) {
        // row-pair interleave: g_ap[(row>>1)*16 + 2k + (row&1)]
        float* dst = g_ap + (row >> 1) * 16 + (row & 1);
#pragma unroll
        for (int k = 0; k < 8; k++) dst[2 * k] = o[k];
    } else {
        // duplicate: g_bd[row*16 + 2k + {0,1}]
        float* dst = g_bd + row * 16;
#pragma unroll
        for (int k = 0; k < 8; k++) { dst[2 * k] = o[k]; dst[2 * k + 1] = o[k]; }
    }
}

// ------------------------------- K2: pairwise ------------------------------
// grid: (nRowBlocks, NCHUNKS). CTA: 256 threads = 16 rowgroups x 16 colgroups.
// Thread: 4 fixed rows (2 packed row-pairs, regs) x 4 cols/step via __ldg.
// No smem b-staging, no barriers in the hot loop.
__global__ __launch_bounds__(256, 4) void pair_kernel(int nsteps) {
    __shared__ float red[64][17];

    const int tid  = threadIdx.x;
    const int lane = tid & 31;
    const int rg   = tid & 15;
    const int cg   = tid >> 4;
    const int bit3 = (lane >> 3) & 1;
    const int bit2 = (lane >> 2) & 1;
    const int row0   = blockIdx.x * 64 + rg * 4;
    const int jbase0 = blockIdx.y * (nsteps * 64);

    // a: two packed row-pairs {a_{r0,k}, a_{r1,k}}, k=0..7 each (128B contig)
    const ulonglong2* gap2 = reinterpret_cast<const ulonglong2*>(g_ap);
    u64 a2[2][8];
#pragma unroll
    for (int rp = 0; rp < 2; rp++) {
#pragma unroll
        for (int q = 0; q < 4; q++) {
            ulonglong2 p = gap2[(size_t)(row0 / 2 + rp) * 4 + q];
            a2[rp][q * 2]     = p.x;
            a2[rp][q * 2 + 1] = p.y;
        }
    }

    const ulonglong2* gbd2 = reinterpret_cast<const ulonglong2*>(g_bd);

    u64 rowacc2[2] = {0ull, 0ull};   // packed {sum_r0, sum_r1} per row-pair

    for (int ts = 0; ts < nsteps; ++ts) {
        const int j0 = jbase0 + ts * 64;
        float cacc[4];
#pragma unroll
        for (int c = 0; c < 4; c++) {
            const int col = j0 + cg * 4 + c;
            const ulonglong2* bcol = gbd2 + (size_t)col * 4;  // 64B column
            ulonglong2 p0 = __ldg(bcol);
            ulonglong2 p1 = __ldg(bcol + 1);
            ulonglong2 p2 = __ldg(bcol + 2);
            ulonglong2 p3 = __ldg(bcol + 3);
            u64 d0 = mul2(a2[0][0], p0.x);
            u64 d1 = mul2(a2[1][0], p0.x);
            d0 = fma2(a2[0][1], p0.y, d0);  d1 = fma2(a2[1][1], p0.y, d1);
            d0 = fma2(a2[0][2], p1.x, d0);  d1 = fma2(a2[1][2], p1.x, d1);
            d0 = fma2(a2[0][3], p1.y, d0);  d1 = fma2(a2[1][3], p1.y, d1);
            d0 = fma2(a2[0][4], p2.x, d0);  d1 = fma2(a2[1][4], p2.x, d1);
            d0 = fma2(a2[0][5], p2.y, d0);  d1 = fma2(a2[1][5], p2.y, d1);
            d0 = fma2(a2[0][6], p3.x, d0);  d1 = fma2(a2[1][6], p3.x, d1);
            d0 = fma2(a2[0][7], p3.y, d0);  d1 = fma2(a2[1][7], p3.y, d1);

            // each half of d0/d1 is a complete dot -> exponentiate per half
            float e00, e01, e10, e11;
            asm("mov.b64 {%0, %1}, %2;" : "=f"(e00), "=f"(e01) : "l"(d0));
            asm("mov.b64 {%0, %1}, %2;" : "=f"(e10), "=f"(e11) : "l"(d1));
            e00 = ex2(e00); e01 = ex2(e01); e10 = ex2(e10); e11 = ex2(e11);
            u64 e2a, e2b;
            asm("mov.b64 %0, {%1, %2};" : "=l"(e2a) : "f"(e00), "f"(e01));
            asm("mov.b64 %0, {%1, %2};" : "=l"(e2b) : "f"(e10), "f"(e11));
            rowacc2[0] = add2(rowacc2[0], e2a);
            rowacc2[1] = add2(rowacc2[1], e2b);
            u64 ecs = add2(e2a, e2b);
            float cl, ch;
            asm("mov.b64 {%0, %1}, %2;" : "=f"(cl), "=f"(ch) : "l"(ecs));
            cacc[c] = cl + ch;
        }

        // value-splitting butterfly over the 16 rg-lanes: 5 shfls total.
        float s0 = bit3 ? cacc[0] : cacc[2];
        s0 = __shfl_xor_sync(0xffffffffu, s0, 8);
        float S0 = (bit3 ? cacc[2] : cacc[0]) + s0;
        float s1 = bit3 ? cacc[1] : cacc[3];
        s1 = __shfl_xor_sync(0xffffffffu, s1, 8);
        float S1 = (bit3 ? cacc[3] : cacc[1]) + s1;
        float s2 = bit2 ? S0 : S1;
        s2 = __shfl_xor_sync(0xffffffffu, s2, 4);
        float T = (bit2 ? S1 : S0) + s2;
        T += __shfl_xor_sync(0xffffffffu, T, 2);
        T += __shfl_xor_sync(0xffffffffu, T, 1);
        // lane (bits1:0 == 0) holds the sum for column cg*4 + bit3*2 + bit2
        if ((lane & 3) == 0)
            atomicAdd(&g_cs[j0 + cg * 4 + bit3 * 2 + bit2], T);
    }

    // unpack packed row sums -> 4 scalar rows, reduce over 16 colgroups
    float ra[4];
    asm("mov.b64 {%0, %1}, %2;" : "=f"(ra[0]), "=f"(ra[1]) : "l"(rowacc2[0]));
    asm("mov.b64 {%0, %1}, %2;" : "=f"(ra[2]), "=f"(ra[3]) : "l"(rowacc2[1]));
#pragma unroll
    for (int r = 0; r < 4; r++) red[rg * 4 + r][cg] = ra[r];
    __syncthreads();
    if (tid < 64) {
        float s = 0.0f;
#pragma unroll
        for (int q = 0; q < 16; q++) s += red[tid][q];
        atomicAdd(&g_rs[blockIdx.x * 64 + tid], s);
    }
}

// ------------------------------- K3: partial + fused combine ---------------
__global__ void partial_kernel(float* __restrict__ out, int N, int nblocks) {
    __shared__ float sh0[256], sh1[256], sh2[256];
    __shared__ bool last;
    const int t = threadIdx.x;
    const int i = blockIdx.x * 256 + t;
    float lr = 0.f, lc = 0.f, dd = 0.f;
    if (i < N) {
        lr = lg2(g_rs[i]);
        lc = lg2(g_cs[i]);
        const float* a = g_ap + (i >> 1) * 16 + (i & 1);
        const float* b = g_bd + i * 16;
        float d = 0.f;
#pragma unroll
        for (int k = 0; k < 8; k++) d = fmaf(a[2 * k], b[2 * k], d);
        dd = d;   // log2-domain diag logit
    }
    sh0[t] = lr; sh1[t] = lc; sh2[t] = dd;
    __syncthreads();
    for (int s = 128; s > 0; s >>= 1) {
        if (t < s) { sh0[t] += sh0[t + s]; sh1[t] += sh1[t + s]; sh2[t] += sh2[t + s]; }
        __syncthreads();
    }
    if (t == 0) {
        atomicAdd(&g_part[0], sh0[0]);
        atomicAdd(&g_part[1], sh1[0]);
        atomicAdd(&g_part[2], sh2[0]);
        __threadfence();
        unsigned int ticket = atomicAdd(&g_cnt, 1u);
        last = (ticket == (unsigned int)(nblocks - 1));
    }
    __syncthreads();
    if (last && t == 0) {
        float p0 = atomicAdd(&g_part[0], 0.0f);
        float p1 = atomicAdd(&g_part[1], 0.0f);
        float p2 = atomicAdd(&g_part[2], 0.0f);
        out[0] = LN2 * (LAM * p0 + (1.0f - LAM) * p1 - p2) / (float)N;
    }
}

// ------------------------------- launch -------------------------------------
extern "C" void kernel_launch(void* const* d_in, const int* in_sizes, int n_in,
                              void* d_out, int out_size) {
    const float* z_mp = (const float*)d_in[0];
    const float* z_sc = (const float*)d_in[1];
    const float* W1   = (const float*)d_in[2];
    const float* b1   = (const float*)d_in[3];
    const float* W2   = (const float*)d_in[4];
    const float* b2   = (const float*)d_in[5];
    float* out = (float*)d_out;

    const int N = in_sizes[0] / 8;

    const int RB = (N + 63) / 64;                              // row blocks
    const int colsPerChunk = ((N + NCHUNKS * 64 - 1) / (NCHUNKS * 64)) * 64;
    const int NpadC = NCHUNKS * colsPerChunk;                  // padded columns
    const int NpadR = RB * 64;                                 // padded rows
    // padded (zero) vectors contribute 2^0 = 1 per pair -> cancel exactly
    const float rs_init = EPS - (float)(NpadC - N);
    const float cs_init = EPS - (float)(NpadR - N);

    const int pthreads = 2 * NpadC;
    proj_kernel<<<(pthreads + 255) / 256, 256>>>(z_mp, z_sc, W1, b1, W2, b2,
                                                 N, NpadC, rs_init, cs_init);

    dim3 grid(RB, NCHUNKS);
    pair_kernel<<<grid, 256>>>(colsPerChunk / 64);

    const int nblocks = (N + 255) / 256;
    partial_kernel<<<nblocks, 256>>>(out, N, nblocks);
}

// round 16
// speedup vs baseline: 1.3120x; 1.3120x over previous
#include <cuda_runtime.h>
#include <cstdint>

// ---------------------------------------------------------------------------
// Contrast loss, fused:
//   a_i = zp1_i/|zp1_i| * (log2e/tau),  b_j = zp2_j/|zp2_j|
//   m[i][j] = 2^(a_i . b_j)
//   loss = LN2*( LAM*sum(lg2 rs) + (1-LAM)*sum(lg2 cs) - sum(a_i.b_i) ) / N
//
// Packed-row trick: g_ap row-pair interleaved {a_{2p,k}, a_{2p+1,k}}, g_bd
// duplicated {b_k, b_k}; one 8-deep fma.f32x2 chain = TWO dots.
//
// Pair kernel: CTA-wide staging with 128-column tiles (8KB), 3-stage
// cp.async ring, ONE barrier per 128 columns (5 per CTA). Thread computes
// 4 fixed rows x 8 cols/step as two independent 4-col groups (ILP).
// LDS.128 column loads + 5-shfl value-splitting butterfly per 4 columns.
// Zero-padded rows/cols contribute 2^0 = 1, cancelled in sum initializers.
// ---------------------------------------------------------------------------

#define TAU   0.5f
#define LAM   0.5f
#define EPS   1e-8f
#define LOG2E 1.4426950408889634f
#define LN2   0.6931471805599453f

#define MAXPAD 16384
#define NCHUNKS 16
#define TILE    128          // columns per step

__device__ __align__(16) float g_ap[MAXPAD * 8];    // row-pair interleaved
__device__ __align__(16) float g_bd[MAXPAD * 16];   // duplicated
__device__ float g_rs[MAXPAD];
__device__ float g_cs[MAXPAD];
__device__ float g_part[3];
__device__ unsigned int g_cnt;

typedef unsigned long long u64;
typedef unsigned int       u32;

__device__ __forceinline__ u32 smem_u32(const void* p) {
    u32 a;
    asm("{ .reg .u64 t; cvta.to.shared.u64 t, %1; cvt.u32.u64 %0, t; }"
        : "=r"(a) : "l"(p));
    return a;
}

__device__ __forceinline__ void cp_async16(u32 saddr, const void* gaddr) {
    asm volatile("cp.async.ca.shared.global [%0], [%1], 16;"
                 :: "r"(saddr), "l"(gaddr) : "memory");
}
__device__ __forceinline__ void cp_commit() {
    asm volatile("cp.async.commit_group;" ::: "memory");
}

__device__ __forceinline__ u64 mul2(u64 a, u64 b) {
    u64 r; asm("mul.rn.f32x2 %0, %1, %2;" : "=l"(r) : "l"(a), "l"(b)); return r;
}
__device__ __forceinline__ u64 fma2(u64 a, u64 b, u64 c) {
    u64 r; asm("fma.rn.f32x2 %0, %1, %2, %3;" : "=l"(r) : "l"(a), "l"(b), "l"(c));
    return r;
}
__device__ __forceinline__ u64 add2(u64 a, u64 b) {
    u64 r; asm("add.rn.f32x2 %0, %1, %2;" : "=l"(r) : "l"(a), "l"(b)); return r;
}

__device__ __forceinline__ float ex2(float x) {
    float r;
    asm("ex2.approx.ftz.f32 %0, %1;" : "=f"(r) : "f"(x));
    return r;
}
__device__ __forceinline__ float lg2(float x) {
    float r;
    asm("lg2.approx.f32 %0, %1;" : "=f"(r) : "f"(x));
    return r;
}

// ------------------------------- K1: projection ----------------------------
__global__ void proj_kernel(const float* __restrict__ z_mp,
                            const float* __restrict__ z_sc,
                            const float* __restrict__ W1,
                            const float* __restrict__ b1,
                            const float* __restrict__ W2,
                            const float* __restrict__ b2,
                            int N, int NpadC, float rs_init, float cs_init) {
    __shared__ float w1s[64], w2s[64], b1s[8], b2s[8];
    int t = threadIdx.x;
    if (t < 64) { w1s[t] = W1[t]; w2s[t] = W2[t]; }
    if (t < 8)  { b1s[t] = b1[t]; b2s[t] = b2[t]; }
    if (blockIdx.x == 0 && t < 3) g_part[t] = 0.0f;
    if (blockIdx.x == 0 && t == 3) g_cnt = 0u;
    __syncthreads();

    int idx = blockIdx.x * blockDim.x + t;
    if (idx >= 2 * NpadC) return;
    int side = (idx >= NpadC) ? 1 : 0;     // 0 = z_mp -> g_ap, 1 = z_sc -> g_bd
    int row  = side ? (idx - NpadC) : idx;

    if (!side) { g_rs[row] = rs_init; g_cs[row] = cs_init; }

    float o[8];
    if (row >= N) {
#pragma unroll
        for (int k = 0; k < 8; k++) o[k] = 0.0f;
    } else {
        const float* z = (side ? z_sc : z_mp) + row * 8;
        float zr[8];
#pragma unroll
        for (int d = 0; d < 8; d++) zr[d] = z[d];

        float h[8];
#pragma unroll
        for (int k = 0; k < 8; k++) {
            float s = b1s[k];
#pragma unroll
            for (int d = 0; d < 8; d++) s = fmaf(zr[d], w1s[k * 8 + d], s);
            h[k] = (s > 0.0f) ? s : (ex2(s * LOG2E) - 1.0f);   // ELU(alpha=1)
        }
        float nn = 0.0f;
#pragma unroll
        for (int j = 0; j < 8; j++) {
            float s = b2s[j];
#pragma unroll
            for (int k = 0; k < 8; k++) s = fmaf(h[k], w2s[j * 8 + k], s);
            o[j] = s;
            nn = fmaf(s, s, nn);
        }
        float scl = (side ? 1.0f : (LOG2E / TAU)) * rsqrtf(nn);
#pragma unroll
        for (int k = 0; k < 8; k++) o[k] *= scl;
    }

    if (!side) {
        // row-pair interleave: g_ap[(row>>1)*16 + 2k + (row&1)]
        float* dst = g_ap + (row >> 1) * 16 + (row & 1);
#pragma unroll
        for (int k = 0; k < 8; k++) dst[2 * k] = o[k];
    } else {
        // duplicate: g_bd[row*16 + 2k + {0,1}]
        float* dst = g_bd + row * 16;
#pragma unroll
        for (int k = 0; k < 8; k++) { dst[2 * k] = o[k]; dst[2 * k + 1] = o[k]; }
    }
}

// ------------------------------- K2: pairwise ------------------------------
// grid: (nRowBlocks, NCHUNKS). CTA: 256 threads = 16 rowgroups x 16 colgroups.
// Thread: 4 fixed rows (2 packed row-pairs, regs) x 8 cols/step from SMEM.
// b tiles: 128 cols x 64B(dup) = 8KB, 3-stage cp.async ring, ONE barrier
// per step. Prefetch distance 2 tiles.
__global__ __launch_bounds__(256, 4) void pair_kernel(int nsteps) {
    __shared__ __align__(16) float bbuf[3][TILE * 16];
    __shared__ float red[64][17];

    const int tid  = threadIdx.x;
    const int lane = tid & 31;
    const int rg   = tid & 15;
    const int cg   = tid >> 4;
    const int bit3 = (lane >> 3) & 1;
    const int bit2 = (lane >> 2) & 1;
    const int row0   = blockIdx.x * 64 + rg * 4;
    const int jbase0 = blockIdx.y * (nsteps * TILE);

    // a: two packed row-pairs {a_{r0,k}, a_{r1,k}}, k=0..7 each
    const ulonglong2* gap2 = reinterpret_cast<const ulonglong2*>(g_ap);
    u64 a2[2][8];
#pragma unroll
    for (int rp = 0; rp < 2; rp++) {
#pragma unroll
        for (int q = 0; q < 4; q++) {
            ulonglong2 p = gap2[(size_t)(row0 / 2 + rp) * 4 + q];
            a2[rp][q * 2]     = p.x;
            a2[rp][q * 2 + 1] = p.y;
        }
    }

    // per-thread slice of each 8KB tile: 32B = 2 x 16B
    const u32 sbase = smem_u32(&bbuf[0][0]) + tid * 32;
    const float* gbp = g_bd + (size_t)jbase0 * 16 + tid * 8;

    // prologue: prefetch up to 2 tiles
    const int npre = (nsteps < 2) ? nsteps : 2;
    for (int s = 0; s < npre; ++s) {
        cp_async16(sbase + s * 8192,      gbp + s * 2048);
        cp_async16(sbase + s * 8192 + 16, gbp + s * 2048 + 4);
        cp_commit();
    }

    u64 rowacc2[2] = {0ull, 0ull};   // packed {sum_r0, sum_r1} per row-pair

    for (int ts = 0; ts < nsteps; ++ts) {
        if (ts < nsteps - 1) asm volatile("cp.async.wait_group 1;" ::: "memory");
        else                 asm volatile("cp.async.wait_group 0;" ::: "memory");
        __syncthreads();
        if (ts + 2 < nsteps) {
            const u32 dst = sbase + ((ts + 2) % 3) * 8192;
            cp_async16(dst,      gbp + (ts + 2) * 2048);
            cp_async16(dst + 16, gbp + (ts + 2) * 2048 + 4);
            cp_commit();
        }

        const ulonglong2* bb =
            reinterpret_cast<const ulonglong2*>(&bbuf[ts % 3][0]);
        const int j0 = jbase0 + ts * TILE;

#pragma unroll
        for (int g = 0; g < 2; g++) {
            float cacc[4];
#pragma unroll
            for (int c = 0; c < 4; c++) {
                const int lc = cg * 8 + g * 4 + c;
                const ulonglong2* bcol = bb + lc * 4;   // 4 x 16B = one column
                ulonglong2 p0 = bcol[0];
                ulonglong2 p1 = bcol[1];
                u64 d0 = mul2(a2[0][0], p0.x);
                u64 d1 = mul2(a2[1][0], p0.x);
                d0 = fma2(a2[0][1], p0.y, d0);  d1 = fma2(a2[1][1], p0.y, d1);
                d0 = fma2(a2[0][2], p1.x, d0);  d1 = fma2(a2[1][2], p1.x, d1);
                d0 = fma2(a2[0][3], p1.y, d0);  d1 = fma2(a2[1][3], p1.y, d1);
                ulonglong2 p2 = bcol[2];
                ulonglong2 p3 = bcol[3];
                d0 = fma2(a2[0][4], p2.x, d0);  d1 = fma2(a2[1][4], p2.x, d1);
                d0 = fma2(a2[0][5], p2.y, d0);  d1 = fma2(a2[1][5], p2.y, d1);
                d0 = fma2(a2[0][6], p3.x, d0);  d1 = fma2(a2[1][6], p3.x, d1);
                d0 = fma2(a2[0][7], p3.y, d0);  d1 = fma2(a2[1][7], p3.y, d1);

                // each half of d0/d1 is a complete dot -> exponentiate per half
                float e00, e01, e10, e11;
                asm("mov.b64 {%0, %1}, %2;" : "=f"(e00), "=f"(e01) : "l"(d0));
                asm("mov.b64 {%0, %1}, %2;" : "=f"(e10), "=f"(e11) : "l"(d1));
                e00 = ex2(e00); e01 = ex2(e01); e10 = ex2(e10); e11 = ex2(e11);
                u64 e2a, e2b;
                asm("mov.b64 %0, {%1, %2};" : "=l"(e2a) : "f"(e00), "f"(e01));
                asm("mov.b64 %0, {%1, %2};" : "=l"(e2b) : "f"(e10), "f"(e11));
                rowacc2[0] = add2(rowacc2[0], e2a);
                rowacc2[1] = add2(rowacc2[1], e2b);
                u64 ecs = add2(e2a, e2b);
                float cl, ch;
                asm("mov.b64 {%0, %1}, %2;" : "=f"(cl), "=f"(ch) : "l"(ecs));
                cacc[c] = cl + ch;
            }

            // value-splitting butterfly over the 16 rg-lanes: 5 shfls total.
            float s0 = bit3 ? cacc[0] : cacc[2];
            s0 = __shfl_xor_sync(0xffffffffu, s0, 8);
            float S0 = (bit3 ? cacc[2] : cacc[0]) + s0;
            float s1 = bit3 ? cacc[1] : cacc[3];
            s1 = __shfl_xor_sync(0xffffffffu, s1, 8);
            float S1 = (bit3 ? cacc[3] : cacc[1]) + s1;
            float s2 = bit2 ? S0 : S1;
            s2 = __shfl_xor_sync(0xffffffffu, s2, 4);
            float T = (bit2 ? S1 : S0) + s2;
            T += __shfl_xor_sync(0xffffffffu, T, 2);
            T += __shfl_xor_sync(0xffffffffu, T, 1);
            // lane (bits1:0 == 0) holds sum for col cg*8 + g*4 + bit3*2 + bit2
            if ((lane & 3) == 0)
                atomicAdd(&g_cs[j0 + cg * 8 + g * 4 + bit3 * 2 + bit2], T);
        }
    }

    // unpack packed row sums -> 4 scalar rows, reduce over 16 colgroups
    float ra[4];
    asm("mov.b64 {%0, %1}, %2;" : "=f"(ra[0]), "=f"(ra[1]) : "l"(rowacc2[0]));
    asm("mov.b64 {%0, %1}, %2;" : "=f"(ra[2]), "=f"(ra[3]) : "l"(rowacc2[1]));
#pragma unroll
    for (int r = 0; r < 4; r++) red[rg * 4 + r][cg] = ra[r];
    __syncthreads();
    if (tid < 64) {
        float s = 0.0f;
#pragma unroll
        for (int q = 0; q < 16; q++) s += red[tid][q];
        atomicAdd(&g_rs[blockIdx.x * 64 + tid], s);
    }
}

// ------------------------------- K3: partial + fused combine ---------------
__global__ void partial_kernel(float* __restrict__ out, int N, int nblocks) {
    __shared__ float sh0[256], sh1[256], sh2[256];
    __shared__ bool last;
    const int t = threadIdx.x;
    const int i = blockIdx.x * 256 + t;
    float lr = 0.f, lc = 0.f, dd = 0.f;
    if (i < N) {
        lr = lg2(g_rs[i]);
        lc = lg2(g_cs[i]);
        const float* a = g_ap + (i >> 1) * 16 + (i & 1);
        const float* b = g_bd + i * 16;
        float d = 0.f;
#pragma unroll
        for (int k = 0; k < 8; k++) d = fmaf(a[2 * k], b[2 * k], d);
        dd = d;   // log2-domain diag logit
    }
    sh0[t] = lr; sh1[t] = lc; sh2[t] = dd;
    __syncthreads();
    for (int s = 128; s > 0; s >>= 1) {
        if (t < s) { sh0[t] += sh0[t + s]; sh1[t] += sh1[t + s]; sh2[t] += sh2[t + s]; }
        __syncthreads();
    }
    if (t == 0) {
        atomicAdd(&g_part[0], sh0[0]);
        atomicAdd(&g_part[1], sh1[0]);
        atomicAdd(&g_part[2], sh2[0]);
        __threadfence();
        unsigned int ticket = atomicAdd(&g_cnt, 1u);
        last = (ticket == (unsigned int)(nblocks - 1));
    }
    __syncthreads();
    if (last && t == 0) {
        float p0 = atomicAdd(&g_part[0], 0.0f);
        float p1 = atomicAdd(&g_part[1], 0.0f);
        float p2 = atomicAdd(&g_part[2], 0.0f);
        out[0] = LN2 * (LAM * p0 + (1.0f - LAM) * p1 - p2) / (float)N;
    }
}

// ------------------------------- launch -------------------------------------
extern "C" void kernel_launch(void* const* d_in, const int* in_sizes, int n_in,
                              void* d_out, int out_size) {
    const float* z_mp = (const float*)d_in[0];
    const float* z_sc = (const float*)d_in[1];
    const float* W1   = (const float*)d_in[2];
    const float* b1   = (const float*)d_in[3];
    const float* W2   = (const float*)d_in[4];
    const float* b2   = (const float*)d_in[5];
    float* out = (float*)d_out;

    const int N = in_sizes[0] / 8;

    const int RB = (N + 63) / 64;                              // row blocks
    const int colsPerChunk =
        ((N + NCHUNKS * TILE - 1) / (NCHUNKS * TILE)) * TILE;
    const int NpadC = NCHUNKS * colsPerChunk;                  // padded columns
    const int NpadR = RB * 64;                                 // padded rows
    // padded (zero) vectors contribute 2^0 = 1 per pair -> cancel exactly
    const float rs_init = EPS - (float)(NpadC - N);
    const float cs_init = EPS - (float)(NpadR - N);

    const int pthreads = 2 * NpadC;
    proj_kernel<<<(pthreads + 255) / 256, 256>>>(z_mp, z_sc, W1, b1, W2, b2,
                                                 N, NpadC, rs_init, cs_init);

    dim3 grid(RB, NCHUNKS);
    pair_kernel<<<grid, 256>>>(colsPerChunk / TILE);

    const int nblocks = (N + 255) / 256;
    partial_kernel<<<nblocks, 256>>>(out, N, nblocks);
}

// round 17
// speedup vs baseline: 1.3159x; 1.0029x over previous
#include <cuda_runtime.h>
#include <cstdint>

// ---------------------------------------------------------------------------
// Contrast loss, fused:
//   a_i = zp1_i/|zp1_i| * (log2e/tau),  b_j = zp2_j/|zp2_j|
//   m[i][j] = 2^(a_i . b_j)
//   loss = LN2*( LAM*sum(lg2 rs) + (1-LAM)*sum(lg2 cs) - sum(a_i.b_i) ) / N
//
// Packed-row trick: g_ap row-pair interleaved {a_{2p,k}, a_{2p+1,k}}, g_bd
// duplicated {b_k, b_k}; one 8-deep fma.f32x2 chain = TWO dots.
//
// Pair kernel: CTA-wide staging with 128-column tiles (8KB), 3-stage
// cp.async ring, ONE barrier per 128 columns (5 per CTA). Thread computes
// 4 fixed rows x 8 cols/step as two independent 4-col groups (ILP).
// LDS.128 column loads + 5-shfl value-splitting butterfly per 4 columns.
// Zero-padded rows/cols contribute 2^0 = 1, cancelled in sum initializers.
// ---------------------------------------------------------------------------

#define TAU   0.5f
#define LAM   0.5f
#define EPS   1e-8f
#define LOG2E 1.4426950408889634f
#define LN2   0.6931471805599453f

#define MAXPAD 16384
#define NCHUNKS 16
#define TILE    128          // columns per step

__device__ __align__(16) float g_ap[MAXPAD * 8];    // row-pair interleaved
__device__ __align__(16) float g_bd[MAXPAD * 16];   // duplicated
__device__ float g_rs[MAXPAD];
__device__ float g_cs[MAXPAD];
__device__ float g_part[3];
__device__ unsigned int g_cnt;

typedef unsigned long long u64;
typedef unsigned int       u32;

__device__ __forceinline__ u32 smem_u32(const void* p) {
    u32 a;
    asm("{ .reg .u64 t; cvta.to.shared.u64 t, %1; cvt.u32.u64 %0, t; }"
        : "=r"(a) : "l"(p));
    return a;
}

__device__ __forceinline__ void cp_async16(u32 saddr, const void* gaddr) {
    asm volatile("cp.async.ca.shared.global [%0], [%1], 16;"
                 :: "r"(saddr), "l"(gaddr) : "memory");
}
__device__ __forceinline__ void cp_commit() {
    asm volatile("cp.async.commit_group;" ::: "memory");
}

__device__ __forceinline__ u64 mul2(u64 a, u64 b) {
    u64 r; asm("mul.rn.f32x2 %0, %1, %2;" : "=l"(r) : "l"(a), "l"(b)); return r;
}
__device__ __forceinline__ u64 fma2(u64 a, u64 b, u64 c) {
    u64 r; asm("fma.rn.f32x2 %0, %1, %2, %3;" : "=l"(r) : "l"(a), "l"(b), "l"(c));
    return r;
}
__device__ __forceinline__ u64 add2(u64 a, u64 b) {
    u64 r; asm("add.rn.f32x2 %0, %1, %2;" : "=l"(r) : "l"(a), "l"(b)); return r;
}

__device__ __forceinline__ float ex2(float x) {
    float r;
    asm("ex2.approx.ftz.f32 %0, %1;" : "=f"(r) : "f"(x));
    return r;
}
__device__ __forceinline__ float lg2(float x) {
    float r;
    asm("lg2.approx.f32 %0, %1;" : "=f"(r) : "f"(x));
    return r;
}

// ------------------------------- K1: projection ----------------------------
__global__ void proj_kernel(const float* __restrict__ z_mp,
                            const float* __restrict__ z_sc,
                            const float* __restrict__ W1,
                            const float* __restrict__ b1,
                            const float* __restrict__ W2,
                            const float* __restrict__ b2,
                            int N, int NpadC, float rs_init, float cs_init) {
    __shared__ float w1s[64], w2s[64], b1s[8], b2s[8];
    int t = threadIdx.x;
    if (t < 64) { w1s[t] = W1[t]; w2s[t] = W2[t]; }
    if (t < 8)  { b1s[t] = b1[t]; b2s[t] = b2[t]; }
    if (blockIdx.x == 0 && t < 3) g_part[t] = 0.0f;
    if (blockIdx.x == 0 && t == 3) g_cnt = 0u;
    __syncthreads();

    int idx = blockIdx.x * blockDim.x + t;
    if (idx >= 2 * NpadC) return;
    int side = (idx >= NpadC) ? 1 : 0;     // 0 = z_mp -> g_ap, 1 = z_sc -> g_bd
    int row  = side ? (idx - NpadC) : idx;

    if (!side) { g_rs[row] = rs_init; g_cs[row] = cs_init; }

    float o[8];
    if (row >= N) {
#pragma unroll
        for (int k = 0; k < 8; k++) o[k] = 0.0f;
    } else {
        const float* z = (side ? z_sc : z_mp) + row * 8;
        float zr[8];
#pragma unroll
        for (int d = 0; d < 8; d++) zr[d] = z[d];

        float h[8];
#pragma unroll
        for (int k = 0; k < 8; k++) {
            float s = b1s[k];
#pragma unroll
            for (int d = 0; d < 8; d++) s = fmaf(zr[d], w1s[k * 8 + d], s);
            h[k] = (s > 0.0f) ? s : (ex2(s * LOG2E) - 1.0f);   // ELU(alpha=1)
        }
        float nn = 0.0f;
#pragma unroll
        for (int j = 0; j < 8; j++) {
            float s = b2s[j];
#pragma unroll
            for (int k = 0; k < 8; k++) s = fmaf(h[k], w2s[j * 8 + k], s);
            o[j] = s;
            nn = fmaf(s, s, nn);
        }
        float scl = (side ? 1.0f : (LOG2E / TAU)) * rsqrtf(nn);
#pragma unroll
        for (int k = 0; k < 8; k++) o[k] *= scl;
    }

    if (!side) {
        // row-pair interleave: g_ap[(row>>1)*16 + 2k + (row&1)]
        float* dst = g_ap + (row >> 1) * 16 + (row & 1);
#pragma unroll
        for (int k = 0; k < 8; k++) dst[2 * k] = o[k];
    } else {
        // duplicate: g_bd[row*16 + 2k + {0,1}]
        float* dst = g_bd + row * 16;
#pragma unroll
        for (int k = 0; k < 8; k++) { dst[2 * k] = o[k]; dst[2 * k + 1] = o[k]; }
    }
}

// ------------------------------- K2: pairwise ------------------------------
// grid: (nRowBlocks, NCHUNKS). CTA: 256 threads = 16 rowgroups x 16 colgroups.
// Thread: 4 fixed rows (2 packed row-pairs, regs) x 8 cols/step from SMEM.
// b tiles: 128 cols x 64B(dup) = 8KB, 3-stage cp.async ring, ONE barrier
// per step. Prefetch distance 2 tiles.
__global__ __launch_bounds__(256, 4) void pair_kernel(int nsteps) {
    __shared__ __align__(16) float bbuf[3][TILE * 16];
    __shared__ float red[64][17];

    const int tid  = threadIdx.x;
    const int lane = tid & 31;
    const int rg   = tid & 15;
    const int cg   = tid >> 4;
    const int bit3 = (lane >> 3) & 1;
    const int bit2 = (lane >> 2) & 1;
    const int row0   = blockIdx.x * 64 + rg * 4;
    const int jbase0 = blockIdx.y * (nsteps * TILE);

    // a: two packed row-pairs {a_{r0,k}, a_{r1,k}}, k=0..7 each
    const ulonglong2* gap2 = reinterpret_cast<const ulonglong2*>(g_ap);
    u64 a2[2][8];
#pragma unroll
    for (int rp = 0; rp < 2; rp++) {
#pragma unroll
        for (int q = 0; q < 4; q++) {
            ulonglong2 p = gap2[(size_t)(row0 / 2 + rp) * 4 + q];
            a2[rp][q * 2]     = p.x;
            a2[rp][q * 2 + 1] = p.y;
        }
    }

    // per-thread slice of each 8KB tile: 32B = 2 x 16B
    const u32 sbase = smem_u32(&bbuf[0][0]) + tid * 32;
    const float* gbp = g_bd + (size_t)jbase0 * 16 + tid * 8;

    // prologue: prefetch up to 2 tiles
    const int npre = (nsteps < 2) ? nsteps : 2;
    for (int s = 0; s < npre; ++s) {
        cp_async16(sbase + s * 8192,      gbp + s * 2048);
        cp_async16(sbase + s * 8192 + 16, gbp + s * 2048 + 4);
        cp_commit();
    }

    u64 rowacc2[2] = {0ull, 0ull};   // packed {sum_r0, sum_r1} per row-pair

    for (int ts = 0; ts < nsteps; ++ts) {
        if (ts < nsteps - 1) asm volatile("cp.async.wait_group 1;" ::: "memory");
        else                 asm volatile("cp.async.wait_group 0;" ::: "memory");
        __syncthreads();
        if (ts + 2 < nsteps) {
            const u32 dst = sbase + ((ts + 2) % 3) * 8192;
            cp_async16(dst,      gbp + (ts + 2) * 2048);
            cp_async16(dst + 16, gbp + (ts + 2) * 2048 + 4);
            cp_commit();
        }

        const ulonglong2* bb =
            reinterpret_cast<const ulonglong2*>(&bbuf[ts % 3][0]);
        const int j0 = jbase0 + ts * TILE;

#pragma unroll
        for (int g = 0; g < 2; g++) {
            float cacc[4];
#pragma unroll
            for (int c = 0; c < 4; c++) {
                const int lc = cg * 8 + g * 4 + c;
                const ulonglong2* bcol = bb + lc * 4;   // 4 x 16B = one column
                ulonglong2 p0 = bcol[0];
                ulonglong2 p1 = bcol[1];
                u64 d0 = mul2(a2[0][0], p0.x);
                u64 d1 = mul2(a2[1][0], p0.x);
                d0 = fma2(a2[0][1], p0.y, d0);  d1 = fma2(a2[1][1], p0.y, d1);
                d0 = fma2(a2[0][2], p1.x, d0);  d1 = fma2(a2[1][2], p1.x, d1);
                d0 = fma2(a2[0][3], p1.y, d0);  d1 = fma2(a2[1][3], p1.y, d1);
                ulonglong2 p2 = bcol[2];
                ulonglong2 p3 = bcol[3];
                d0 = fma2(a2[0][4], p2.x, d0);  d1 = fma2(a2[1][4], p2.x, d1);
                d0 = fma2(a2[0][5], p2.y, d0);  d1 = fma2(a2[1][5], p2.y, d1);
                d0 = fma2(a2[0][6], p3.x, d0);  d1 = fma2(a2[1][6], p3.x, d1);
                d0 = fma2(a2[0][7], p3.y, d0);  d1 = fma2(a2[1][7], p3.y, d1);

                // each half of d0/d1 is a complete dot -> exponentiate per half
                float e00, e01, e10, e11;
                asm("mov.b64 {%0, %1}, %2;" : "=f"(e00), "=f"(e01) : "l"(d0));
                asm("mov.b64 {%0, %1}, %2;" : "=f"(e10), "=f"(e11) : "l"(d1));
                e00 = ex2(e00); e01 = ex2(e01); e10 = ex2(e10); e11 = ex2(e11);
                u64 e2a, e2b;
                asm("mov.b64 %0, {%1, %2};" : "=l"(e2a) : "f"(e00), "f"(e01));
                asm("mov.b64 %0, {%1, %2};" : "=l"(e2b) : "f"(e10), "f"(e11));
                rowacc2[0] = add2(rowacc2[0], e2a);
                rowacc2[1] = add2(rowacc2[1], e2b);
                u64 ecs = add2(e2a, e2b);
                float cl, ch;
                asm("mov.b64 {%0, %1}, %2;" : "=f"(cl), "=f"(ch) : "l"(ecs));
                cacc[c] = cl + ch;
            }

            // value-splitting butterfly over the 16 rg-lanes: 5 shfls total.
            float s0 = bit3 ? cacc[0] : cacc[2];
            s0 = __shfl_xor_sync(0xffffffffu, s0, 8);
            float S0 = (bit3 ? cacc[2] : cacc[0]) + s0;
            float s1 = bit3 ? cacc[1] : cacc[3];
            s1 = __shfl_xor_sync(0xffffffffu, s1, 8);
            float S1 = (bit3 ? cacc[3] : cacc[1]) + s1;
            float s2 = bit2 ? S0 : S1;
            s2 = __shfl_xor_sync(0xffffffffu, s2, 4);
            float T = (bit2 ? S1 : S0) + s2;
            T += __shfl_xor_sync(0xffffffffu, T, 2);
            T += __shfl_xor_sync(0xffffffffu, T, 1);
            // lane (bits1:0 == 0) holds sum for col cg*8 + g*4 + bit3*2 + bit2
            if ((lane & 3) == 0)
                atomicAdd(&g_cs[j0 + cg * 8 + g * 4 + bit3 * 2 + bit2], T);
        }
    }

    // unpack packed row sums -> 4 scalar rows, reduce over 16 colgroups
    float ra[4];
    asm("mov.b64 {%0, %1}, %2;" : "=f"(ra[0]), "=f"(ra[1]) : "l"(rowacc2[0]));
    asm("mov.b64 {%0, %1}, %2;" : "=f"(ra[2]), "=f"(ra[3]) : "l"(rowacc2[1]));
#pragma unroll
    for (int r = 0; r < 4; r++) red[rg * 4 + r][cg] = ra[r];
    __syncthreads();
    if (tid < 64) {
        float s = 0.0f;
#pragma unroll
        for (int q = 0; q < 16; q++) s += red[tid][q];
        atomicAdd(&g_rs[blockIdx.x * 64 + tid], s);
    }
}

// ------------------------------- K3: partial + fused combine ---------------
__global__ void partial_kernel(float* __restrict__ out, int N, int nblocks) {
    __shared__ float sh0[256], sh1[256], sh2[256];
    __shared__ bool last;
    const int t = threadIdx.x;
    const int i = blockIdx.x * 256 + t;
    float lr = 0.f, lc = 0.f, dd = 0.f;
    if (i < N) {
        lr = lg2(g_rs[i]);
        lc = lg2(g_cs[i]);
        const float* a = g_ap + (i >> 1) * 16 + (i & 1);
        const float* b = g_bd + i * 16;
        float d = 0.f;
#pragma unroll
        for (int k = 0; k < 8; k++) d = fmaf(a[2 * k], b[2 * k], d);
        dd = d;   // log2-domain diag logit
    }
    sh0[t] = lr; sh1[t] = lc; sh2[t] = dd;
    __syncthreads();
    for (int s = 128; s > 0; s >>= 1) {
        if (t < s) { sh0[t] += sh0[t + s]; sh1[t] += sh1[t + s]; sh2[t] += sh2[t + s]; }
        __syncthreads();
    }
    if (t == 0) {
        atomicAdd(&g_part[0], sh0[0]);
        atomicAdd(&g_part[1], sh1[0]);
        atomicAdd(&g_part[2], sh2[0]);
        __threadfence();
        unsigned int ticket = atomicAdd(&g_cnt, 1u);
        last = (ticket == (unsigned int)(nblocks - 1));
    }
    __syncthreads();
    if (last && t == 0) {
        float p0 = atomicAdd(&g_part[0], 0.0f);
        float p1 = atomicAdd(&g_part[1], 0.0f);
        float p2 = atomicAdd(&g_part[2], 0.0f);
        out[0] = LN2 * (LAM * p0 + (1.0f - LAM) * p1 - p2) / (float)N;
    }
}

// ------------------------------- launch -------------------------------------
extern "C" void kernel_launch(void* const* d_in, const int* in_sizes, int n_in,
                              void* d_out, int out_size) {
    const float* z_mp = (const float*)d_in[0];
    const float* z_sc = (const float*)d_in[1];
    const float* W1   = (const float*)d_in[2];
    const float* b1   = (const float*)d_in[3];
    const float* W2   = (const float*)d_in[4];
    const float* b2   = (const float*)d_in[5];
    float* out = (float*)d_out;

    const int N = in_sizes[0] / 8;

    const int RB = (N + 63) / 64;                              // row blocks
    const int colsPerChunk =
        ((N + NCHUNKS * TILE - 1) / (NCHUNKS * TILE)) * TILE;
    const int NpadC = NCHUNKS * colsPerChunk;                  // padded columns
    const int NpadR = RB * 64;                                 // padded rows
    // padded (zero) vectors contribute 2^0 = 1 per pair -> cancel exactly
    const float rs_init = EPS - (float)(NpadC - N);
    const float cs_init = EPS - (float)(NpadR - N);

    const int pthreads = 2 * NpadC;
    proj_kernel<<<(pthreads + 255) / 256, 256>>>(z_mp, z_sc, W1, b1, W2, b2,
                                                 N, NpadC, rs_init, cs_init);

    dim3 grid(RB, NCHUNKS);
    pair_kernel<<<grid, 256>>>(colsPerChunk / TILE);

    const int nblocks = (N + 255) / 256;
    partial_kernel<<<nblocks, 256>>>(out, N, nblocks);
}